// round 7
// baseline (speedup 1.0000x reference)
#include <cuda_runtime.h>

#define NR 1024
#define NC 1024
#define NN (NR*NC)

#define TS   32              // output tile side
#define H    6               // halo (6 one-ring stages)
#define REG  44              // TS + 2*H
#define REG2 (REG*REG)
#define NQ   21              // quads per dim (rows/cols [1,43) in 2x2 quads)
#define NQUAD (NQ*NQ)        // 441
#define NTHR 448

// persistent scratch
__device__ float g_Wp[NN * 8];  // interleaved per-point weights [i*8 + o]
__device__ float g_yA[NN];
__device__ float g_yB[NN];

// Tsit5 coefficients
#define DT (1.0f/32.0f)
#define A21  0.161f
#define A31 -0.008480655492356989f
#define A32  0.335480655492357f
#define A41  2.8971530571054935f
#define A42 -6.359448489975075f
#define A43  4.3622954328695815f
#define A51  5.325864828439257f
#define A52 -11.748883564062828f
#define A53  7.4955393428898365f
#define A54 -0.09249506636175525f
#define A61  5.86145544294642f
#define A62 -12.92096931784711f
#define A63  8.159367898576159f
#define A64 -0.071584973281401f
#define A65 -0.028269050394068383f
#define B1   0.09646076681806523f
#define B2   0.01f
#define B3   0.4798896504144996f
#define B4   1.379008574103742f
#define B5  -3.290069515436081f
#define B6   2.324710524099774f

__device__ __forceinline__ float act(float v) {
    // fmaxf/fminf drop NaN operands -> sanitizes halo garbage too
    return fminf(1.0f, fmaxf(-1.0f, v));
}

__global__ void init_kernel(const float* __restrict__ x) {
    int i = blockIdx.x * blockDim.x + threadIdx.x;
    if (i >= NN) return;
    g_yA[i] = x[i];
#pragma unroll
    for (int o = 0; o < 8; o++) g_Wp[i * 8 + o] = 0.0f;
}

// Scatter edge weights into interleaved per-dst slots keyed by (dst-src) offset.
__global__ void scatter_W(const float* __restrict__ k,
                          const int* __restrict__ src,
                          const int* __restrict__ dst, int ne) {
    int e = blockIdx.x * blockDim.x + threadIdx.x;
    if (e >= ne) return;
    int j = src[e], i = dst[e];
    int dr = (i >> 10) - (j >> 10);      // pos(dst) - pos(src)
    int dc = (i & 1023) - (j & 1023);
    int idx = (dr + 1) * 3 + (dc + 1);   // 0..8, center (4) never occurs
    int o = (idx > 4) ? idx - 1 : idx;   // 0..7
    g_Wp[i * 8 + o] = k[e];
}

// Weight slot o pairs with source-neighbor offset (relative to point r,c):
// o0:(r+1,c+1) o1:(r+1,c) o2:(r+1,c-1) o3:(r,c+1) o4:(r,c-1)
// o5:(r-1,c+1) o6:(r-1,c) o7:(r-1,c-1)
//
// Quad points: 0=(rr,cc) 1=(rr,cc+1) 2=(rr+1,cc) 3=(rr+1,cc+1); cc odd.
// smem holds act(u); own 4 acts live in registers.
template<int S>
__device__ __forceinline__ void do_stage(
    const float* __restrict__ uc, float* __restrict__ un,
    bool valid, int p00,
    const float w[4][8], float kk[4][5],
    float uu[4], float aa[4],
    const float yy[4], const float zz[4],
    const bool inn[4], const int gg[4],
    float* __restrict__ y_out, float* __restrict__ fin)
{
    if (!valid) return;

    // 4x4 act-neighborhood, 12 loaded + 4 own registers
    float2 tm0 = *(const float2*)(uc + p00 - REG - 1);      // (rr-1, cc-1..cc)
    float2 tm1 = *(const float2*)(uc + p00 - REG + 1);      // (rr-1, cc+1..cc+2)
    float2 bt0 = *(const float2*)(uc + p00 + 2*REG - 1);    // (rr+2, cc-1..cc)
    float2 bt1 = *(const float2*)(uc + p00 + 2*REG + 1);    // (rr+2, cc+1..cc+2)
    float  l0  = uc[p00 - 1];                               // (rr,   cc-1)
    float  r0v = uc[p00 + 2];                               // (rr,   cc+2)
    float  l1  = uc[p00 + REG - 1];                         // (rr+1, cc-1)
    float  r1v = uc[p00 + REG + 2];                         // (rr+1, cc+2)
    float t0 = tm0.x, t1 = tm0.y, t2 = tm1.x, t3 = tm1.y;
    float b0 = bt0.x, b1 = bt0.y, b2 = bt1.x, b3 = bt1.y;

    float s0 = zz[0] - uu[0];
    s0 = fmaf(w[0][0], aa[3], s0); s0 = fmaf(w[0][1], aa[2], s0);
    s0 = fmaf(w[0][2], l1,    s0); s0 = fmaf(w[0][3], aa[1], s0);
    s0 = fmaf(w[0][4], l0,    s0); s0 = fmaf(w[0][5], t2,    s0);
    s0 = fmaf(w[0][6], t1,    s0); s0 = fmaf(w[0][7], t0,    s0);

    float s1 = zz[1] - uu[1];
    s1 = fmaf(w[1][0], r1v,   s1); s1 = fmaf(w[1][1], aa[3], s1);
    s1 = fmaf(w[1][2], aa[2], s1); s1 = fmaf(w[1][3], r0v,   s1);
    s1 = fmaf(w[1][4], aa[0], s1); s1 = fmaf(w[1][5], t3,    s1);
    s1 = fmaf(w[1][6], t2,    s1); s1 = fmaf(w[1][7], t1,    s1);

    float s2 = zz[2] - uu[2];
    s2 = fmaf(w[2][0], b2,    s2); s2 = fmaf(w[2][1], b1,    s2);
    s2 = fmaf(w[2][2], b0,    s2); s2 = fmaf(w[2][3], aa[3], s2);
    s2 = fmaf(w[2][4], l1,    s2); s2 = fmaf(w[2][5], aa[1], s2);
    s2 = fmaf(w[2][6], aa[0], s2); s2 = fmaf(w[2][7], l0,    s2);

    float s3 = zz[3] - uu[3];
    s3 = fmaf(w[3][0], b3,    s3); s3 = fmaf(w[3][1], b2,    s3);
    s3 = fmaf(w[3][2], b1,    s3); s3 = fmaf(w[3][3], r1v,   s3);
    s3 = fmaf(w[3][4], aa[2], s3); s3 = fmaf(w[3][5], r0v,   s3);
    s3 = fmaf(w[3][6], aa[1], s3); s3 = fmaf(w[3][7], aa[0], s3);

    float s[4] = {s0, s1, s2, s3};

    if (S == 6) { // final B-combination -> global y (or clipped output)
#pragma unroll
        for (int q = 0; q < 4; q++) {
            if (inn[q]) {
                float yn = fmaf(DT, B1*kk[q][0] + B2*kk[q][1] + B3*kk[q][2]
                                  + B4*kk[q][3] + B5*kk[q][4] + B6*s[q], yy[q]);
                if (fin) fin[gg[q]] = fminf(1.0f, fmaxf(-1.0f, yn));
                else     y_out[gg[q]] = yn;
            }
        }
        return;
    }

#pragma unroll
    for (int q = 0; q < 4; q++) {
        float nu;
        if (S == 1)      { kk[q][0] = s[q]; nu = fmaf(DT, A21 * s[q], yy[q]); }
        else if (S == 2) { kk[q][1] = s[q]; nu = fmaf(DT, A31*kk[q][0] + A32*s[q], yy[q]); }
        else if (S == 3) { kk[q][2] = s[q]; nu = fmaf(DT, A41*kk[q][0] + A42*kk[q][1] + A43*s[q], yy[q]); }
        else if (S == 4) { kk[q][3] = s[q]; nu = fmaf(DT, A51*kk[q][0] + A52*kk[q][1] + A53*kk[q][2] + A54*s[q], yy[q]); }
        else             { kk[q][4] = s[q]; nu = fmaf(DT, A61*kk[q][0] + A62*kk[q][1] + A63*kk[q][2] + A64*kk[q][3] + A65*s[q], yy[q]); }
        uu[q] = nu;
        aa[q] = act(nu);
    }
    un[p00]           = aa[0];
    un[p00 + 1]       = aa[1];
    un[p00 + REG]     = aa[2];
    un[p00 + REG + 1] = aa[3];
}

// One full Tsit5 step for a 32x32 tile with halo-6 redundant compute.
// Thread owns a 2x2 quad; smem (act values) ping-pongs over 2 buffers.
__global__ void __launch_bounds__(NTHR)
step_kernel(int par, const float* __restrict__ z, float* __restrict__ fin) {
    __shared__ __align__(16) float sA_buf[REG2];   // act(u) ping
    __shared__ __align__(16) float sB_buf[REG2];   // act(u) pong

    const float* __restrict__ y_in  = par ? g_yB : g_yA;
    float*       __restrict__ y_out = par ? g_yA : g_yB;

    const int tid = threadIdx.x;
    const int r0 = (int)blockIdx.y * TS - H;
    const int c0 = (int)blockIdx.x * TS - H;

    // fill ping buffer with act(y) (zero-padded OOB); zero pong buffer
    for (int p = tid; p < REG2; p += NTHR) {
        int lr = p / REG, lc = p - lr * REG;
        int r = r0 + lr, c = c0 + lc;
        bool in = ((unsigned)r < NR) & ((unsigned)c < NC);
        sA_buf[p] = in ? act(y_in[r * NC + c]) : 0.0f;
        sB_buf[p] = 0.0f;
    }

    // quad assignment: rows (rr, rr+1), cols (cc, cc+1); rr = 1+2qr, cc = 1+2qc
    const bool valid = tid < NQUAD;
    int qt = valid ? tid : 0;
    int qr = qt / NQ;
    int qc = qt - qr * NQ;
    int rr = 1 + 2 * qr;
    int cc = 1 + 2 * qc;
    int p00 = rr * REG + cc;

    float yy[4], zz[4], w[4][8];
    int gg[4];
    bool inn[4];

#pragma unroll
    for (int q = 0; q < 4; q++) {
        int lr = rr + (q >> 1);
        int lc = cc + (q & 1);
        int r = r0 + lr, c = c0 + lc;
        bool in = valid & ((unsigned)r < NR) & ((unsigned)c < NC);
        int g = in ? (r * NC + c) : 0;
        gg[q]  = g;
        inn[q] = valid & (lr >= H) & (lr < H + TS) & (lc >= H) & (lc < H + TS);
        zz[q]  = in ? __ldg(&z[g])    : 0.0f;
        yy[q]  = in ? __ldg(&y_in[g]) : 0.0f;
        float4 w0 = in ? *(const float4*)(g_Wp + (size_t)g * 8)     : make_float4(0,0,0,0);
        float4 w1 = in ? *(const float4*)(g_Wp + (size_t)g * 8 + 4) : make_float4(0,0,0,0);
        w[q][0]=w0.x; w[q][1]=w0.y; w[q][2]=w0.z; w[q][3]=w0.w;
        w[q][4]=w1.x; w[q][5]=w1.y; w[q][6]=w1.z; w[q][7]=w1.w;
    }

    float uu[4], aa[4], kk[4][5];
#pragma unroll
    for (int q = 0; q < 4; q++) { uu[q] = yy[q]; aa[q] = act(yy[q]); }

    __syncthreads();

    do_stage<1>(sA_buf, sB_buf, valid, p00, w, kk, uu, aa, yy, zz, inn, gg, y_out, fin);
    __syncthreads();
    do_stage<2>(sB_buf, sA_buf, valid, p00, w, kk, uu, aa, yy, zz, inn, gg, y_out, fin);
    __syncthreads();
    do_stage<3>(sA_buf, sB_buf, valid, p00, w, kk, uu, aa, yy, zz, inn, gg, y_out, fin);
    __syncthreads();
    do_stage<4>(sB_buf, sA_buf, valid, p00, w, kk, uu, aa, yy, zz, inn, gg, y_out, fin);
    __syncthreads();
    do_stage<5>(sA_buf, sB_buf, valid, p00, w, kk, uu, aa, yy, zz, inn, gg, y_out, fin);
    __syncthreads();
    do_stage<6>(sB_buf, sA_buf, valid, p00, w, kk, uu, aa, yy, zz, inn, gg, y_out, fin);
}

extern "C" void kernel_launch(void* const* d_in, const int* in_sizes, int n_in,
                              void* d_out, int out_size) {
    const float* x   = (const float*)d_in[0];
    const float* z   = (const float*)d_in[1];
    const float* k   = (const float*)d_in[2];
    const int*   src = (const int*)d_in[3];
    const int*   dst = (const int*)d_in[4];
    int ne = in_sizes[2];

    init_kernel<<<(NN + 511) / 512, 512>>>(x);
    scatter_W<<<(ne + 511) / 512, 512>>>(k, src, dst, ne);

    dim3 grid(NC / TS, NR / TS);   // 32 x 32 tiles
    for (int s = 0; s < 32; s++) {
        float* fin = (s == 31) ? (float*)d_out : nullptr;  // last step: fused clip -> d_out
        step_kernel<<<grid, NTHR>>>(s & 1, z, fin);
    }
}

// round 8
// speedup vs baseline: 1.0034x; 1.0034x over previous
#include <cuda_runtime.h>

#define NR 1024
#define NC 1024
#define NN (NR*NC)

#define TS   24              // output tile side
#define H    6               // halo (6 one-ring stages)
#define REG  36              // TS + 2*H
#define REG2 (REG*REG)
#define NPR  17              // column-pairs per region row
#define NROWS 34             // region rows [1,35)
#define NPAIR (NPR*NROWS)    // 578
#define NTHR 608
#define NTILE ((NR + TS - 1) / TS)   // 43

// persistent scratch
__device__ float g_Wp[NN * 8];  // interleaved per-point weights [i*8 + o]
__device__ float g_yA[NN];
__device__ float g_yB[NN];

// Tsit5 coefficients
#define DT (1.0f/32.0f)
#define A21  0.161f
#define A31 -0.008480655492356989f
#define A32  0.335480655492357f
#define A41  2.8971530571054935f
#define A42 -6.359448489975075f
#define A43  4.3622954328695815f
#define A51  5.325864828439257f
#define A52 -11.748883564062828f
#define A53  7.4955393428898365f
#define A54 -0.09249506636175525f
#define A61  5.86145544294642f
#define A62 -12.92096931784711f
#define A63  8.159367898576159f
#define A64 -0.071584973281401f
#define A65 -0.028269050394068383f
#define B1   0.09646076681806523f
#define B2   0.01f
#define B3   0.4798896504144996f
#define B4   1.379008574103742f
#define B5  -3.290069515436081f
#define B6   2.324710524099774f

__device__ __forceinline__ float act(float v) {
    // fmaxf/fminf drop NaN operands -> sanitizes halo garbage too
    return fminf(1.0f, fmaxf(-1.0f, v));
}

__global__ void init_kernel(const float* __restrict__ x) {
    int i = blockIdx.x * blockDim.x + threadIdx.x;
    if (i >= NN) return;
    g_yA[i] = x[i];
#pragma unroll
    for (int o = 0; o < 8; o++) g_Wp[i * 8 + o] = 0.0f;
}

// Scatter edge weights into interleaved per-dst slots keyed by (dst-src) offset.
__global__ void scatter_W(const float* __restrict__ k,
                          const int* __restrict__ src,
                          const int* __restrict__ dst, int ne) {
    int e = blockIdx.x * blockDim.x + threadIdx.x;
    if (e >= ne) return;
    int j = src[e], i = dst[e];
    int dr = (i >> 10) - (j >> 10);      // pos(dst) - pos(src)
    int dc = (i & 1023) - (j & 1023);
    int idx = (dr + 1) * 3 + (dc + 1);   // 0..8, center (4) never occurs
    int o = (idx > 4) ? idx - 1 : idx;   // 0..7
    g_Wp[i * 8 + o] = k[e];
}

// One stage for a horizontally-adjacent point pair (A at p, B at p+1), lc odd.
// smem buffers hold act(u); raw u + act(u) of own points live in registers.
// Weight slot o (offset = dst-src) pairs with source neighbor at p - loff[o].
template<int S>
__device__ __forceinline__ void do_stage(
    const float* __restrict__ uc, float* __restrict__ un,
    bool valid, int p,
    const float wA[8], const float wB[8],
    float kA[5], float kB[5],
    float& uAc, float& uBc, float& aAc, float& aBc,
    float yA, float yB, float zA, float zB,
    bool innA, bool innB, int gA, int gB,
    float* __restrict__ y_out, float* __restrict__ fin)
{
    if (!valid) return;

    // pre-activated neighbor values from smem
    float2 am = *(const float2*)(uc + p - REG - 1);  // row-1, cols lc-1,lc
    float2 bm = *(const float2*)(uc + p - REG + 1);  // row-1, cols lc+1,lc+2
    float2 ap = *(const float2*)(uc + p + REG - 1);  // row+1, cols lc-1,lc
    float2 bp = *(const float2*)(uc + p + REG + 1);  // row+1, cols lc+1,lc+2
    float  lA = uc[p - 1];                           // row  , col lc-1
    float  rB = uc[p + 2];                           // row  , col lc+2

    // Point A (center p): s = z - u + sum_o w[o] * act(u[p - loff[o]])
    float sA = zA - uAc;
    sA = fmaf(wA[0], bp.x, sA);   // src p+REG+1
    sA = fmaf(wA[1], ap.y, sA);   // p+REG
    sA = fmaf(wA[2], ap.x, sA);   // p+REG-1
    sA = fmaf(wA[3], aBc,  sA);   // p+1  (own pair partner, in-register)
    sA = fmaf(wA[4], lA,   sA);   // p-1
    sA = fmaf(wA[5], bm.x, sA);   // p-REG+1
    sA = fmaf(wA[6], am.y, sA);   // p-REG
    sA = fmaf(wA[7], am.x, sA);   // p-REG-1

    // Point B (center p+1)
    float sB = zB - uBc;
    sB = fmaf(wB[0], bp.y, sB);   // p+REG+2
    sB = fmaf(wB[1], bp.x, sB);   // p+REG+1
    sB = fmaf(wB[2], ap.y, sB);   // p+REG
    sB = fmaf(wB[3], rB,   sB);   // p+2
    sB = fmaf(wB[4], aAc,  sB);   // p    (own pair partner, in-register)
    sB = fmaf(wB[5], bm.y, sB);   // p-REG+2
    sB = fmaf(wB[6], bm.x, sB);   // p-REG+1
    sB = fmaf(wB[7], am.y, sB);   // p-REG

    if (S == 6) { // final B-combination -> global y (or clipped output)
        if (innA) {
            float yn = fmaf(DT, B1*kA[0] + B2*kA[1] + B3*kA[2]
                              + B4*kA[3] + B5*kA[4] + B6*sA, yA);
            if (fin) fin[gA] = fminf(1.0f, fmaxf(-1.0f, yn));
            else     y_out[gA] = yn;
        }
        if (innB) {
            float yn = fmaf(DT, B1*kB[0] + B2*kB[1] + B3*kB[2]
                              + B4*kB[3] + B5*kB[4] + B6*sB, yB);
            if (fin) fin[gB] = fminf(1.0f, fmaxf(-1.0f, yn));
            else     y_out[gB] = yn;
        }
        return;
    }

    float nuA, nuB;
    if (S == 1) {
        kA[0] = sA; kB[0] = sB;
        nuA = fmaf(DT, A21 * sA, yA);
        nuB = fmaf(DT, A21 * sB, yB);
    } else if (S == 2) {
        kA[1] = sA; kB[1] = sB;
        nuA = fmaf(DT, A31*kA[0] + A32*sA, yA);
        nuB = fmaf(DT, A31*kB[0] + A32*sB, yB);
    } else if (S == 3) {
        kA[2] = sA; kB[2] = sB;
        nuA = fmaf(DT, A41*kA[0] + A42*kA[1] + A43*sA, yA);
        nuB = fmaf(DT, A41*kB[0] + A42*kB[1] + A43*sB, yB);
    } else if (S == 4) {
        kA[3] = sA; kB[3] = sB;
        nuA = fmaf(DT, A51*kA[0] + A52*kA[1] + A53*kA[2] + A54*sA, yA);
        nuB = fmaf(DT, A51*kB[0] + A52*kB[1] + A53*kB[2] + A54*sB, yB);
    } else { // S == 5
        kA[4] = sA; kB[4] = sB;
        nuA = fmaf(DT, A61*kA[0] + A62*kA[1] + A63*kA[2] + A64*kA[3] + A65*sA, yA);
        nuB = fmaf(DT, A61*kB[0] + A62*kB[1] + A63*kB[2] + A64*kB[3] + A65*sB, yB);
    }
    uAc = nuA;  aAc = act(nuA);
    uBc = nuB;  aBc = act(nuB);
    un[p]     = aAc;
    un[p + 1] = aBc;
}

// One full Tsit5 step for a 24x24 tile with halo-6 redundant compute.
// 2 CTAs/SM so barrier drains overlap across independent blocks.
__global__ void __launch_bounds__(NTHR, 2)
step_kernel(int par, const float* __restrict__ z, float* __restrict__ fin) {
    __shared__ __align__(16) float sA_buf[REG2];   // act(u) ping
    __shared__ __align__(16) float sB_buf[REG2];   // act(u) pong

    const float* __restrict__ y_in  = par ? g_yB : g_yA;
    float*       __restrict__ y_out = par ? g_yA : g_yB;

    const int tid = threadIdx.x;
    const int r0 = (int)blockIdx.y * TS - H;
    const int c0 = (int)blockIdx.x * TS - H;

    // fill ping buffer with act(y) (zero-padded OOB); zero pong buffer
    for (int p = tid; p < REG2; p += NTHR) {
        int lr = p / REG, lc = p - lr * REG;
        int r = r0 + lr, c = c0 + lc;
        bool in = ((unsigned)r < NR) & ((unsigned)c < NC);
        sA_buf[p] = in ? act(y_in[r * NC + c]) : 0.0f;
        sB_buf[p] = 0.0f;
    }

    // per-thread pair assignment: row lr in [1,35), cols (lc, lc+1), lc odd
    const bool valid = tid < NPAIR;
    int qt = valid ? tid : 0;
    int pr = qt / NPR;
    int pc = qt - pr * NPR;
    int lr = 1 + pr;
    int lc = 1 + 2 * pc;
    int p  = lr * REG + lc;

    int rA = r0 + lr, cA = c0 + lc, cB = cA + 1;
    bool inA = valid & ((unsigned)rA < NR) & ((unsigned)cA < NC);
    bool inB = valid & ((unsigned)rA < NR) & ((unsigned)cB < NC);
    int gA = inA ? (rA * NC + cA) : 0;
    int gB = inB ? (rA * NC + cB) : 0;
    // inner mask: tile-local inner region AND inside the global grid
    bool innA = inA & (lr >= H) & (lr < H + TS) & (lc   >= H) & (lc   < H + TS);
    bool innB = inB & (lr >= H) & (lr < H + TS) & (lc+1 >= H) & (lc+1 < H + TS);

    float zA = inA ? __ldg(&z[gA]) : 0.0f;
    float zB = inB ? __ldg(&z[gB]) : 0.0f;
    float yA = inA ? __ldg(&y_in[gA]) : 0.0f;
    float yB = inB ? __ldg(&y_in[gB]) : 0.0f;

    float wA[8], wB[8];
    {
        float4 a0 = inA ? *(const float4*)(g_Wp + (size_t)gA * 8)     : make_float4(0,0,0,0);
        float4 a1 = inA ? *(const float4*)(g_Wp + (size_t)gA * 8 + 4) : make_float4(0,0,0,0);
        float4 b0 = inB ? *(const float4*)(g_Wp + (size_t)gB * 8)     : make_float4(0,0,0,0);
        float4 b1 = inB ? *(const float4*)(g_Wp + (size_t)gB * 8 + 4) : make_float4(0,0,0,0);
        wA[0]=a0.x; wA[1]=a0.y; wA[2]=a0.z; wA[3]=a0.w;
        wA[4]=a1.x; wA[5]=a1.y; wA[6]=a1.z; wA[7]=a1.w;
        wB[0]=b0.x; wB[1]=b0.y; wB[2]=b0.z; wB[3]=b0.w;
        wB[4]=b1.x; wB[5]=b1.y; wB[6]=b1.z; wB[7]=b1.w;
    }

    float uAc = yA, uBc = yB;
    float aAc = act(yA), aBc = act(yB);
    float kA[5], kB[5];

    __syncthreads();

    do_stage<1>(sA_buf, sB_buf, valid, p, wA, wB, kA, kB, uAc, uBc, aAc, aBc,
                yA, yB, zA, zB, innA, innB, gA, gB, y_out, fin);
    __syncthreads();
    do_stage<2>(sB_buf, sA_buf, valid, p, wA, wB, kA, kB, uAc, uBc, aAc, aBc,
                yA, yB, zA, zB, innA, innB, gA, gB, y_out, fin);
    __syncthreads();
    do_stage<3>(sA_buf, sB_buf, valid, p, wA, wB, kA, kB, uAc, uBc, aAc, aBc,
                yA, yB, zA, zB, innA, innB, gA, gB, y_out, fin);
    __syncthreads();
    do_stage<4>(sB_buf, sA_buf, valid, p, wA, wB, kA, kB, uAc, uBc, aAc, aBc,
                yA, yB, zA, zB, innA, innB, gA, gB, y_out, fin);
    __syncthreads();
    do_stage<5>(sA_buf, sB_buf, valid, p, wA, wB, kA, kB, uAc, uBc, aAc, aBc,
                yA, yB, zA, zB, innA, innB, gA, gB, y_out, fin);
    __syncthreads();
    do_stage<6>(sB_buf, sA_buf, valid, p, wA, wB, kA, kB, uAc, uBc, aAc, aBc,
                yA, yB, zA, zB, innA, innB, gA, gB, y_out, fin);
}

extern "C" void kernel_launch(void* const* d_in, const int* in_sizes, int n_in,
                              void* d_out, int out_size) {
    const float* x   = (const float*)d_in[0];
    const float* z   = (const float*)d_in[1];
    const float* k   = (const float*)d_in[2];
    const int*   src = (const int*)d_in[3];
    const int*   dst = (const int*)d_in[4];
    int ne = in_sizes[2];

    init_kernel<<<(NN + 511) / 512, 512>>>(x);
    scatter_W<<<(ne + 511) / 512, 512>>>(k, src, dst, ne);

    dim3 grid(NTILE, NTILE);   // 43 x 43 tiles of 24x24
    for (int s = 0; s < 32; s++) {
        float* fin = (s == 31) ? (float*)d_out : nullptr;  // last step: fused clip -> d_out
        step_kernel<<<grid, NTHR>>>(s & 1, z, fin);
    }
}

// round 9
// speedup vs baseline: 1.0363x; 1.0328x over previous
#include <cuda_runtime.h>

#define NR 1024
#define NC 1024
#define NN (NR*NC)

#define TS   24              // output tile side
#define H    6               // halo (6 one-ring stages)
#define REG  36              // TS + 2*H
#define REG2 (REG*REG)
#define NPR  17              // column-pairs per region row
#define NROWS 34             // region rows [1,35)
#define NPAIR (NPR*NROWS)    // 578
#define NTHR 608
#define NTILE ((NR + TS - 1) / TS)   // 43

// persistent scratch
__device__ float g_Wp[NN * 8];  // interleaved per-point weights [i*8 + o]
__device__ float g_yA[NN];
__device__ float g_yB[NN];

// Tsit5 coefficients
#define DT (1.0f/32.0f)
#define A21  0.161f
#define A31 -0.008480655492356989f
#define A32  0.335480655492357f
#define A41  2.8971530571054935f
#define A42 -6.359448489975075f
#define A43  4.3622954328695815f
#define A51  5.325864828439257f
#define A52 -11.748883564062828f
#define A53  7.4955393428898365f
#define A54 -0.09249506636175525f
#define A61  5.86145544294642f
#define A62 -12.92096931784711f
#define A63  8.159367898576159f
#define A64 -0.071584973281401f
#define A65 -0.028269050394068383f
#define B1   0.09646076681806523f
#define B2   0.01f
#define B3   0.4798896504144996f
#define B4   1.379008574103742f
#define B5  -3.290069515436081f
#define B6   2.324710524099774f

__device__ __forceinline__ float act(float v) {
    // fmaxf/fminf drop NaN operands -> sanitizes halo garbage too
    return fminf(1.0f, fmaxf(-1.0f, v));
}

__global__ void init_kernel(const float* __restrict__ x) {
    int i = blockIdx.x * blockDim.x + threadIdx.x;
    if (i >= NN) return;
    g_yA[i] = x[i];
#pragma unroll
    for (int o = 0; o < 8; o++) g_Wp[i * 8 + o] = 0.0f;
}

// Scatter edge weights into interleaved per-dst slots keyed by (dst-src) offset.
__global__ void scatter_W(const float* __restrict__ k,
                          const int* __restrict__ src,
                          const int* __restrict__ dst, int ne) {
    int e = blockIdx.x * blockDim.x + threadIdx.x;
    if (e >= ne) return;
    int j = src[e], i = dst[e];
    int dr = (i >> 10) - (j >> 10);      // pos(dst) - pos(src)
    int dc = (i & 1023) - (j & 1023);
    int idx = (dr + 1) * 3 + (dc + 1);   // 0..8, center (4) never occurs
    int o = (idx > 4) ? idx - 1 : idx;   // 0..7
    g_Wp[i * 8 + o] = k[e];
}

// One stage for a horizontally-adjacent point pair (A at p, B at p+1), lc odd.
// smem buffers hold act(u); raw u + act(u) of own points live in registers.
// Weight slot o (offset = dst-src) pairs with source neighbor at p - loff[o].
// Active region shrinks with S: rows/cols [S, REG-S).
template<int S>
__device__ __forceinline__ void do_stage(
    const float* __restrict__ uc, float* __restrict__ un,
    bool valid, int p, int lr, int lc,
    const float wA[8], const float wB[8],
    float kA[5], float kB[5],
    float& uAc, float& uBc, float& aAc, float& aBc,
    float yA, float yB, float zA, float zB,
    bool innA, bool innB, int gA, int gB,
    float* __restrict__ y_out, float* __restrict__ fin)
{
    // pair active iff its row is in [S, REG-S) and its columns intersect it
    bool active = valid & (lr >= S) & (lr < REG - S)
                        & (lc + 1 >= S) & (lc <= REG - 1 - S);
    if (!active) return;

    // pre-activated neighbor values from smem
    float2 am = *(const float2*)(uc + p - REG - 1);  // row-1, cols lc-1,lc
    float2 bm = *(const float2*)(uc + p - REG + 1);  // row-1, cols lc+1,lc+2
    float2 ap = *(const float2*)(uc + p + REG - 1);  // row+1, cols lc-1,lc
    float2 bp = *(const float2*)(uc + p + REG + 1);  // row+1, cols lc+1,lc+2
    float  lA = uc[p - 1];                           // row  , col lc-1
    float  rB = uc[p + 2];                           // row  , col lc+2

    // Point A (center p): s = z - u + sum_o w[o] * act(u[p - loff[o]])
    float sA = zA - uAc;
    sA = fmaf(wA[0], bp.x, sA);   // src p+REG+1
    sA = fmaf(wA[1], ap.y, sA);   // p+REG
    sA = fmaf(wA[2], ap.x, sA);   // p+REG-1
    sA = fmaf(wA[3], aBc,  sA);   // p+1  (own pair partner, in-register)
    sA = fmaf(wA[4], lA,   sA);   // p-1
    sA = fmaf(wA[5], bm.x, sA);   // p-REG+1
    sA = fmaf(wA[6], am.y, sA);   // p-REG
    sA = fmaf(wA[7], am.x, sA);   // p-REG-1

    // Point B (center p+1)
    float sB = zB - uBc;
    sB = fmaf(wB[0], bp.y, sB);   // p+REG+2
    sB = fmaf(wB[1], bp.x, sB);   // p+REG+1
    sB = fmaf(wB[2], ap.y, sB);   // p+REG
    sB = fmaf(wB[3], rB,   sB);   // p+2
    sB = fmaf(wB[4], aAc,  sB);   // p    (own pair partner, in-register)
    sB = fmaf(wB[5], bm.y, sB);   // p-REG+2
    sB = fmaf(wB[6], bm.x, sB);   // p-REG+1
    sB = fmaf(wB[7], am.y, sB);   // p-REG

    if (S == 6) { // final B-combination -> global y (or clipped output)
        if (innA) {
            float yn = fmaf(DT, B1*kA[0] + B2*kA[1] + B3*kA[2]
                              + B4*kA[3] + B5*kA[4] + B6*sA, yA);
            if (fin) fin[gA] = fminf(1.0f, fmaxf(-1.0f, yn));
            else     y_out[gA] = yn;
        }
        if (innB) {
            float yn = fmaf(DT, B1*kB[0] + B2*kB[1] + B3*kB[2]
                              + B4*kB[3] + B5*kB[4] + B6*sB, yB);
            if (fin) fin[gB] = fminf(1.0f, fmaxf(-1.0f, yn));
            else     y_out[gB] = yn;
        }
        return;
    }

    float nuA, nuB;
    if (S == 1) {
        kA[0] = sA; kB[0] = sB;
        nuA = fmaf(DT, A21 * sA, yA);
        nuB = fmaf(DT, A21 * sB, yB);
    } else if (S == 2) {
        kA[1] = sA; kB[1] = sB;
        nuA = fmaf(DT, A31*kA[0] + A32*sA, yA);
        nuB = fmaf(DT, A31*kB[0] + A32*sB, yB);
    } else if (S == 3) {
        kA[2] = sA; kB[2] = sB;
        nuA = fmaf(DT, A41*kA[0] + A42*kA[1] + A43*sA, yA);
        nuB = fmaf(DT, A41*kB[0] + A42*kB[1] + A43*sB, yB);
    } else if (S == 4) {
        kA[3] = sA; kB[3] = sB;
        nuA = fmaf(DT, A51*kA[0] + A52*kA[1] + A53*kA[2] + A54*sA, yA);
        nuB = fmaf(DT, A51*kB[0] + A52*kB[1] + A53*kB[2] + A54*sB, yB);
    } else { // S == 5
        kA[4] = sA; kB[4] = sB;
        nuA = fmaf(DT, A61*kA[0] + A62*kA[1] + A63*kA[2] + A64*kA[3] + A65*sA, yA);
        nuB = fmaf(DT, A61*kB[0] + A62*kB[1] + A63*kB[2] + A64*kB[3] + A65*sB, yB);
    }
    uAc = nuA;  aAc = act(nuA);
    uBc = nuB;  aBc = act(nuB);
    un[p]     = aAc;
    un[p + 1] = aBc;
}

// One full Tsit5 step for a 24x24 tile with halo-6 redundant compute;
// active region shrinks by one ring per stage.
__global__ void __launch_bounds__(NTHR, 2)
step_kernel(int par, const float* __restrict__ z, float* __restrict__ fin) {
    __shared__ __align__(16) float sA_buf[REG2];   // act(u) ping
    __shared__ __align__(16) float sB_buf[REG2];   // act(u) pong

    const float* __restrict__ y_in  = par ? g_yB : g_yA;
    float*       __restrict__ y_out = par ? g_yA : g_yB;

    const int tid = threadIdx.x;
    const int r0 = (int)blockIdx.y * TS - H;
    const int c0 = (int)blockIdx.x * TS - H;

    // fill ping buffer with act(y) (zero-padded OOB), division-free walker.
    // NTHR = 16*REG + 32, so per iteration: lr += 16, lc += 32 (with wrap).
    {
        int flr = tid / REG;
        int flc = tid - flr * REG;
        int p = tid;
        while (p < REG2) {
            int r = r0 + flr, c = c0 + flc;
            bool in = ((unsigned)r < NR) & ((unsigned)c < NC);
            sA_buf[p] = in ? act(y_in[r * NC + c]) : 0.0f;
            p += NTHR;
            flr += 16; flc += 32;
            if (flc >= REG) { flc -= REG; flr += 1; }
        }
    }

    // per-thread pair assignment: row lr in [1,35), cols (lc, lc+1), lc odd
    const bool valid = tid < NPAIR;
    int qt = valid ? tid : 0;
    int pr = qt / NPR;
    int pc = qt - pr * NPR;
    int lr = 1 + pr;
    int lc = 1 + 2 * pc;
    int p  = lr * REG + lc;

    int rA = r0 + lr, cA = c0 + lc, cB = cA + 1;
    bool inA = valid & ((unsigned)rA < NR) & ((unsigned)cA < NC);
    bool inB = valid & ((unsigned)rA < NR) & ((unsigned)cB < NC);
    int gA = inA ? (rA * NC + cA) : 0;
    int gB = inB ? (rA * NC + cB) : 0;
    // inner mask: tile-local inner region AND inside the global grid
    bool innA = inA & (lr >= H) & (lr < H + TS) & (lc   >= H) & (lc   < H + TS);
    bool innB = inB & (lr >= H) & (lr < H + TS) & (lc+1 >= H) & (lc+1 < H + TS);

    float zA = inA ? __ldg(&z[gA]) : 0.0f;
    float zB = inB ? __ldg(&z[gB]) : 0.0f;
    float yA = inA ? __ldg(&y_in[gA]) : 0.0f;
    float yB = inB ? __ldg(&y_in[gB]) : 0.0f;

    float wA[8], wB[8];
    {
        float4 a0 = inA ? *(const float4*)(g_Wp + (size_t)gA * 8)     : make_float4(0,0,0,0);
        float4 a1 = inA ? *(const float4*)(g_Wp + (size_t)gA * 8 + 4) : make_float4(0,0,0,0);
        float4 b0 = inB ? *(const float4*)(g_Wp + (size_t)gB * 8)     : make_float4(0,0,0,0);
        float4 b1 = inB ? *(const float4*)(g_Wp + (size_t)gB * 8 + 4) : make_float4(0,0,0,0);
        wA[0]=a0.x; wA[1]=a0.y; wA[2]=a0.z; wA[3]=a0.w;
        wA[4]=a1.x; wA[5]=a1.y; wA[6]=a1.z; wA[7]=a1.w;
        wB[0]=b0.x; wB[1]=b0.y; wB[2]=b0.z; wB[3]=b0.w;
        wB[4]=b1.x; wB[5]=b1.y; wB[6]=b1.z; wB[7]=b1.w;
    }

    float uAc = yA, uBc = yB;
    float aAc = act(yA), aBc = act(yB);
    float kA[5], kB[5];

    __syncthreads();

    do_stage<1>(sA_buf, sB_buf, valid, p, lr, lc, wA, wB, kA, kB, uAc, uBc, aAc, aBc,
                yA, yB, zA, zB, innA, innB, gA, gB, y_out, fin);
    __syncthreads();
    do_stage<2>(sB_buf, sA_buf, valid, p, lr, lc, wA, wB, kA, kB, uAc, uBc, aAc, aBc,
                yA, yB, zA, zB, innA, innB, gA, gB, y_out, fin);
    __syncthreads();
    do_stage<3>(sA_buf, sB_buf, valid, p, lr, lc, wA, wB, kA, kB, uAc, uBc, aAc, aBc,
                yA, yB, zA, zB, innA, innB, gA, gB, y_out, fin);
    __syncthreads();
    do_stage<4>(sB_buf, sA_buf, valid, p, lr, lc, wA, wB, kA, kB, uAc, uBc, aAc, aBc,
                yA, yB, zA, zB, innA, innB, gA, gB, y_out, fin);
    __syncthreads();
    do_stage<5>(sA_buf, sB_buf, valid, p, lr, lc, wA, wB, kA, kB, uAc, uBc, aAc, aBc,
                yA, yB, zA, zB, innA, innB, gA, gB, y_out, fin);
    __syncthreads();
    do_stage<6>(sB_buf, sA_buf, valid, p, lr, lc, wA, wB, kA, kB, uAc, uBc, aAc, aBc,
                yA, yB, zA, zB, innA, innB, gA, gB, y_out, fin);
}

extern "C" void kernel_launch(void* const* d_in, const int* in_sizes, int n_in,
                              void* d_out, int out_size) {
    const float* x   = (const float*)d_in[0];
    const float* z   = (const float*)d_in[1];
    const float* k   = (const float*)d_in[2];
    const int*   src = (const int*)d_in[3];
    const int*   dst = (const int*)d_in[4];
    int ne = in_sizes[2];

    init_kernel<<<(NN + 511) / 512, 512>>>(x);
    scatter_W<<<(ne + 511) / 512, 512>>>(k, src, dst, ne);

    dim3 grid(NTILE, NTILE);   // 43 x 43 tiles of 24x24
    for (int s = 0; s < 32; s++) {
        float* fin = (s == 31) ? (float*)d_out : nullptr;  // last step: fused clip -> d_out
        step_kernel<<<grid, NTHR>>>(s & 1, z, fin);
    }
}

// round 10
// speedup vs baseline: 1.3183x; 1.2721x over previous
#include <cuda_runtime.h>

#define NR 1024
#define NC 1024
#define NN (NR*NC)

#define TS   24              // output tile side
#define H    6               // halo (6 one-ring stages)
#define REG  36              // TS + 2*H
#define REG2 (REG*REG)
#define NPR  18              // column-pairs per region row (even lc: 0..34)
#define NROWS 34             // region rows [1,35)
#define NPAIR (NPR*NROWS)    // 612
#define NTHR 640
#define NTILE ((NR + TS - 1) / TS)   // 43
#define SBUF (REG2 + 2*REG)  // one guard row each side

// persistent scratch
__device__ float g_W[8 * NN];   // planar per-offset weights [o][i]
__device__ float g_yA[NN];
__device__ float g_yB[NN];

// Tsit5 coefficients
#define DT (1.0f/32.0f)
#define A21  0.161f
#define A31 -0.008480655492356989f
#define A32  0.335480655492357f
#define A41  2.8971530571054935f
#define A42 -6.359448489975075f
#define A43  4.3622954328695815f
#define A51  5.325864828439257f
#define A52 -11.748883564062828f
#define A53  7.4955393428898365f
#define A54 -0.09249506636175525f
#define A61  5.86145544294642f
#define A62 -12.92096931784711f
#define A63  8.159367898576159f
#define A64 -0.071584973281401f
#define A65 -0.028269050394068383f
#define B1   0.09646076681806523f
#define B2   0.01f
#define B3   0.4798896504144996f
#define B4   1.379008574103742f
#define B5  -3.290069515436081f
#define B6   2.324710524099774f

__device__ __forceinline__ float act(float v) {
    // fmaxf/fminf drop NaN operands -> sanitizes halo garbage too
    return fminf(1.0f, fmaxf(-1.0f, v));
}

__global__ void init_kernel(const float* __restrict__ x) {
    int i = blockIdx.x * blockDim.x + threadIdx.x;
    if (i >= NN) return;
    g_yA[i] = x[i];
#pragma unroll
    for (int o = 0; o < 8; o++) g_W[o * NN + i] = 0.0f;
}

// Scatter edge weights into planar per-dst planes keyed by (dst-src) offset.
__global__ void scatter_W(const float* __restrict__ k,
                          const int* __restrict__ src,
                          const int* __restrict__ dst, int ne) {
    int e = blockIdx.x * blockDim.x + threadIdx.x;
    if (e >= ne) return;
    int j = src[e], i = dst[e];
    int dr = (i >> 10) - (j >> 10);      // pos(dst) - pos(src)
    int dc = (i & 1023) - (j & 1023);
    int idx = (dr + 1) * 3 + (dc + 1);   // 0..8, center (4) never occurs
    int o = (idx > 4) ? idx - 1 : idx;   // 0..7
    g_W[o * NN + i] = k[e];
}

// One stage for a horizontally-adjacent point pair (A at p, B at p+1), lc even.
// smem buffers hold act(u); raw u + act(u) of own points live in registers.
// Weight slot o (offset = dst-src) pairs with source neighbor at p - loff[o].
// Active region shrinks with S: rows/cols [S, REG-S).
template<int S>
__device__ __forceinline__ void do_stage(
    const float* __restrict__ uc, float* __restrict__ un,
    bool valid, int p, int lr, int lc,
    const float wA[8], const float wB[8],
    float kA[5], float kB[5],
    float& uAc, float& uBc, float& aAc, float& aBc,
    float yA, float yB, float zA, float zB,
    bool innA, bool innB, int gA, int gB,
    float* __restrict__ y_out, float* __restrict__ fin)
{
    // pair active iff its row is in [S, REG-S) and its columns intersect it
    bool active = valid & (lr >= S) & (lr < REG - S)
                        & (lc + 1 >= S) & (lc <= REG - 1 - S);
    if (!active) return;

    // pre-activated neighbor values from smem (lc even -> p-1 odd, p+... mixed;
    // use float2 where the base is even: p-REG, p+REG, and scalars elsewhere)
    float2 am = *(const float2*)(uc + p - REG);      // row-1, cols lc,lc+1
    float2 ap = *(const float2*)(uc + p + REG);      // row+1, cols lc,lc+1
    float  amL = uc[p - REG - 1];                    // row-1, col lc-1
    float  amR = uc[p - REG + 2];                    // row-1, col lc+2
    float  apL = uc[p + REG - 1];                    // row+1, col lc-1
    float  apR = uc[p + REG + 2];                    // row+1, col lc+2
    float  lA  = uc[p - 1];                          // row  , col lc-1
    float  rB  = uc[p + 2];                          // row  , col lc+2

    // Point A (center p): s = z - u + sum_o w[o] * act(u[p - loff[o]])
    float sA = zA - uAc;
    sA = fmaf(wA[0], ap.y, sA);   // src p+REG+1
    sA = fmaf(wA[1], ap.x, sA);   // p+REG
    sA = fmaf(wA[2], apL,  sA);   // p+REG-1
    sA = fmaf(wA[3], aBc,  sA);   // p+1  (own pair partner, in-register)
    sA = fmaf(wA[4], lA,   sA);   // p-1
    sA = fmaf(wA[5], am.y, sA);   // p-REG+1
    sA = fmaf(wA[6], am.x, sA);   // p-REG
    sA = fmaf(wA[7], amL,  sA);   // p-REG-1

    // Point B (center p+1)
    float sB = zB - uBc;
    sB = fmaf(wB[0], apR,  sB);   // p+REG+2
    sB = fmaf(wB[1], ap.y, sB);   // p+REG+1
    sB = fmaf(wB[2], ap.x, sB);   // p+REG
    sB = fmaf(wB[3], rB,   sB);   // p+2
    sB = fmaf(wB[4], aAc,  sB);   // p    (own pair partner, in-register)
    sB = fmaf(wB[5], amR,  sB);   // p-REG+2
    sB = fmaf(wB[6], am.y, sB);   // p-REG+1
    sB = fmaf(wB[7], am.x, sB);   // p-REG

    if (S == 6) { // final B-combination -> global y (or clipped output)
        if (innA) {
            float yn = fmaf(DT, B1*kA[0] + B2*kA[1] + B3*kA[2]
                              + B4*kA[3] + B5*kA[4] + B6*sA, yA);
            if (fin) fin[gA] = fminf(1.0f, fmaxf(-1.0f, yn));
            else     y_out[gA] = yn;
        }
        if (innB) {
            float yn = fmaf(DT, B1*kB[0] + B2*kB[1] + B3*kB[2]
                              + B4*kB[3] + B5*kB[4] + B6*sB, yB);
            if (fin) fin[gB] = fminf(1.0f, fmaxf(-1.0f, yn));
            else     y_out[gB] = yn;
        }
        return;
    }

    float nuA, nuB;
    if (S == 1) {
        kA[0] = sA; kB[0] = sB;
        nuA = fmaf(DT, A21 * sA, yA);
        nuB = fmaf(DT, A21 * sB, yB);
    } else if (S == 2) {
        kA[1] = sA; kB[1] = sB;
        nuA = fmaf(DT, A31*kA[0] + A32*sA, yA);
        nuB = fmaf(DT, A31*kB[0] + A32*sB, yB);
    } else if (S == 3) {
        kA[2] = sA; kB[2] = sB;
        nuA = fmaf(DT, A41*kA[0] + A42*kA[1] + A43*sA, yA);
        nuB = fmaf(DT, A41*kB[0] + A42*kB[1] + A43*sB, yB);
    } else if (S == 4) {
        kA[3] = sA; kB[3] = sB;
        nuA = fmaf(DT, A51*kA[0] + A52*kA[1] + A53*kA[2] + A54*sA, yA);
        nuB = fmaf(DT, A51*kB[0] + A52*kB[1] + A53*kB[2] + A54*sB, yB);
    } else { // S == 5
        kA[4] = sA; kB[4] = sB;
        nuA = fmaf(DT, A61*kA[0] + A62*kA[1] + A63*kA[2] + A64*kA[3] + A65*sA, yA);
        nuB = fmaf(DT, A61*kB[0] + A62*kB[1] + A63*kB[2] + A64*kB[3] + A65*sB, yB);
    }
    uAc = nuA;  aAc = act(nuA);
    uBc = nuB;  aBc = act(nuB);
    *(float2*)(un + p) = make_float2(aAc, aBc);   // p even -> aligned
}

// One full Tsit5 step for a 24x24 tile with halo-6 redundant compute;
// active region shrinks by one ring per stage. Coalesced prologue loads.
__global__ void __launch_bounds__(NTHR, 2)
step_kernel(int par, const float* __restrict__ z, float* __restrict__ fin) {
    __shared__ __align__(16) float sA_raw[SBUF];   // act(u) ping (+guards)
    __shared__ __align__(16) float sB_raw[SBUF];   // act(u) pong (+guards)
    float* const sA_buf = sA_raw + REG;
    float* const sB_buf = sB_raw + REG;

    const float* __restrict__ y_in  = par ? g_yB : g_yA;
    float*       __restrict__ y_out = par ? g_yA : g_yB;

    const int tid = threadIdx.x;
    const int r0 = (int)blockIdx.y * TS - H;
    const int c0 = (int)blockIdx.x * TS - H;

    // zero guard rows of both buffers + pong body; fill ping body with act(y).
    for (int p = tid; p < SBUF; p += NTHR) sB_raw[p] = 0.0f;
    if (tid < REG) { sA_raw[tid] = 0.0f; sA_raw[SBUF - REG + tid] = 0.0f; }
    {
        // division-free walker: NTHR = 17*REG + 28
        int flr = tid / REG;
        int flc = tid - flr * REG;
        int p = tid;
        while (p < REG2) {
            int r = r0 + flr, c = c0 + flc;
            bool in = ((unsigned)r < NR) & ((unsigned)c < NC);
            sA_buf[p] = in ? act(y_in[r * NC + c]) : 0.0f;
            p += NTHR;
            flc += 28;
            if (flc >= REG) { flc -= REG; flr += 1; }
            flr += 17;
        }
    }

    // per-thread pair assignment: row lr in [1,35), cols (lc, lc+1), lc EVEN
    const bool valid = tid < NPAIR;
    int qt = valid ? tid : 0;
    int pr = qt / NPR;
    int pc = qt - pr * NPR;
    int lr = 1 + pr;
    int lc = 2 * pc;            // 0,2,...,34
    int p  = lr * REG + lc;

    int rA = r0 + lr, cA = c0 + lc, cB = cA + 1;
    bool inA = valid & ((unsigned)rA < NR) & ((unsigned)cA < NC);
    bool inB = valid & ((unsigned)rA < NR) & ((unsigned)cB < NC);
    int gA = inA ? (rA * NC + cA) : 0;   // gA even when inA (cA = c0+lc even)
    int gB = inB ? (rA * NC + cB) : 0;
    // pair-vector loads valid only if BOTH points in grid (row in range and
    // cB in range; cA<NC follows). gA is float2-aligned.
    bool inAB = inA & inB;
    // inner mask: tile-local inner region AND inside the global grid
    bool innA = inA & (lr >= H) & (lr < H + TS) & (lc   >= H) & (lc   < H + TS);
    bool innB = inB & (lr >= H) & (lr < H + TS) & (lc+1 >= H) & (lc+1 < H + TS);

    float zA, zB, yA, yB;
    if (inAB) {
        float2 zv = *(const float2*)(z + gA);
        float2 yv = *(const float2*)(y_in + gA);
        zA = zv.x; zB = zv.y; yA = yv.x; yB = yv.y;
    } else {
        zA = inA ? __ldg(&z[gA]) : 0.0f;
        zB = inB ? __ldg(&z[gB]) : 0.0f;
        yA = inA ? __ldg(&y_in[gA]) : 0.0f;
        yB = inB ? __ldg(&y_in[gB]) : 0.0f;
    }

    float wA[8], wB[8];
    if (inAB) {
#pragma unroll
        for (int o = 0; o < 8; o++) {
            float2 wv = *(const float2*)(g_W + (size_t)o * NN + gA);
            wA[o] = wv.x; wB[o] = wv.y;
        }
    } else {
#pragma unroll
        for (int o = 0; o < 8; o++) {
            wA[o] = inA ? g_W[(size_t)o * NN + gA] : 0.0f;
            wB[o] = inB ? g_W[(size_t)o * NN + gB] : 0.0f;
        }
    }

    float uAc = yA, uBc = yB;
    float aAc = act(yA), aBc = act(yB);
    float kA[5], kB[5];

    __syncthreads();

    do_stage<1>(sA_buf, sB_buf, valid, p, lr, lc, wA, wB, kA, kB, uAc, uBc, aAc, aBc,
                yA, yB, zA, zB, innA, innB, gA, gB, y_out, fin);
    __syncthreads();
    do_stage<2>(sB_buf, sA_buf, valid, p, lr, lc, wA, wB, kA, kB, uAc, uBc, aAc, aBc,
                yA, yB, zA, zB, innA, innB, gA, gB, y_out, fin);
    __syncthreads();
    do_stage<3>(sA_buf, sB_buf, valid, p, lr, lc, wA, wB, kA, kB, uAc, uBc, aAc, aBc,
                yA, yB, zA, zB, innA, innB, gA, gB, y_out, fin);
    __syncthreads();
    do_stage<4>(sB_buf, sA_buf, valid, p, lr, lc, wA, wB, kA, kB, uAc, uBc, aAc, aBc,
                yA, yB, zA, zB, innA, innB, gA, gB, y_out, fin);
    __syncthreads();
    do_stage<5>(sA_buf, sB_buf, valid, p, lr, lc, wA, wB, kA, kB, uAc, uBc, aAc, aBc,
                yA, yB, zA, zB, innA, innB, gA, gB, y_out, fin);
    __syncthreads();
    do_stage<6>(sB_buf, sA_buf, valid, p, lr, lc, wA, wB, kA, kB, uAc, uBc, aAc, aBc,
                yA, yB, zA, zB, innA, innB, gA, gB, y_out, fin);
}

extern "C" void kernel_launch(void* const* d_in, const int* in_sizes, int n_in,
                              void* d_out, int out_size) {
    const float* x   = (const float*)d_in[0];
    const float* z   = (const float*)d_in[1];
    const float* k   = (const float*)d_in[2];
    const int*   src = (const int*)d_in[3];
    const int*   dst = (const int*)d_in[4];
    int ne = in_sizes[2];

    init_kernel<<<(NN + 511) / 512, 512>>>(x);
    scatter_W<<<(ne + 511) / 512, 512>>>(k, src, dst, ne);

    dim3 grid(NTILE, NTILE);   // 43 x 43 tiles of 24x24
    for (int s = 0; s < 32; s++) {
        float* fin = (s == 31) ? (float*)d_out : nullptr;  // last step: fused clip -> d_out
        step_kernel<<<grid, NTHR>>>(s & 1, z, fin);
    }
}